// round 1
// baseline (speedup 1.0000x reference)
#include <cuda_runtime.h>
#include <math.h>

#define B_   8
#define C_   512
#define G_   4
#define D_   128
#define H_   128
#define W_   128
#define WF_  65
#define F_   (H_*WF_)        // 8320
#define NIMG (B_*C_)         // 4096
#define TF_  64              // frequency tile in mixer

// Scratch (allocation-free requirement -> device globals). ~545MB total.
static __device__ float g_specR[(size_t)NIMG * F_];
static __device__ float g_specI[(size_t)NIMG * F_];
static __device__ float g_outR [(size_t)NIMG * F_];
static __device__ float g_outI [(size_t)NIMG * F_];

#define PITCH 129

// ---------------------------------------------------------------------------
// Forward: per (b,c) image, 2D FFT (natural order), keep wf 0..64, scale 1/128
// ---------------------------------------------------------------------------
__global__ void __launch_bounds__(256) kfft_fwd(const float* __restrict__ x) {
    extern __shared__ float sm[];
    float* sR  = sm;                     // 128*129
    float* sI  = sR + 128 * PITCH;       // 128*129
    float* twR = sI + 128 * PITCH;       // 64
    float* twI = twR + 64;               // 64

    const int tid = threadIdx.x;
    const int img = blockIdx.x;

    if (tid < 64) {
        float s, c;
        sincospif(-2.0f * (float)tid / 128.0f, &s, &c);  // exp(-2*pi*i*t/128)
        twR[tid] = c; twI[tid] = s;
    }

    // Load image, bit-reverse columns (w) on the fly
    const float* src = x + (size_t)img * (H_ * W_);
    for (int t = tid; t < H_ * W_; t += 256) {
        int r = t >> 7, c = t & 127;
        int rc = __brev((unsigned)c) >> 25;              // 7-bit reversal
        sR[r * PITCH + rc] = src[t];
        sI[r * PITCH + rc] = 0.0f;
    }
    __syncthreads();

    // Row FFTs (along w), all 128 rows, DIT radix-2
    for (int s = 1; s <= 7; s++) {
        int half = 1 << (s - 1);
        for (int t = tid; t < 128 * 64; t += 256) {
            int r = t >> 6, bf = t & 63;
            int j = bf & (half - 1);
            int base = (bf >> (s - 1)) << s;
            int i1 = r * PITCH + base + j;
            int i2 = i1 + half;
            int ti_ = j << (7 - s);
            float wr = twR[ti_], wi = twI[ti_];
            float ar = sR[i1], ai = sI[i1];
            float br = sR[i2], bi = sI[i2];
            float tr = br * wr - bi * wi;
            float tq = br * wi + bi * wr;
            sR[i1] = ar + tr; sI[i1] = ai + tq;
            sR[i2] = ar - tr; sI[i2] = ai - tq;
        }
        __syncthreads();
    }

    // Bit-reverse rows (h) for the kept 65 columns
    for (int t = tid; t < 128 * WF_; t += 256) {
        int r = t / WF_, c = t - r * WF_;
        int rb = __brev((unsigned)r) >> 25;
        if (rb > r) {
            float a;
            a = sR[r * PITCH + c]; sR[r * PITCH + c] = sR[rb * PITCH + c]; sR[rb * PITCH + c] = a;
            a = sI[r * PITCH + c]; sI[r * PITCH + c] = sI[rb * PITCH + c]; sI[rb * PITCH + c] = a;
        }
    }
    __syncthreads();

    // Column FFTs (along h) on 65 columns
    for (int s = 1; s <= 7; s++) {
        int half = 1 << (s - 1);
        for (int t = tid; t < WF_ * 64; t += 256) {
            int c = t % WF_, bf = t / WF_;
            int j = bf & (half - 1);
            int base = (bf >> (s - 1)) << s;
            int i1 = (base + j) * PITCH + c;
            int i2 = i1 + half * PITCH;
            int ti_ = j << (7 - s);
            float wr = twR[ti_], wi = twI[ti_];
            float ar = sR[i1], ai = sI[i1];
            float br = sR[i2], bi = sI[i2];
            float tr = br * wr - bi * wi;
            float tq = br * wi + bi * wr;
            sR[i1] = ar + tr; sI[i1] = ai + tq;
            sR[i2] = ar - tr; sI[i2] = ai - tq;
        }
        __syncthreads();
    }

    // Store spectrum (ortho: /sqrt(H*W) = /128)
    float* dR = g_specR + (size_t)img * F_;
    float* dI = g_specI + (size_t)img * F_;
    const float scale = 1.0f / 128.0f;
    for (int t = tid; t < F_; t += 256) {
        int h = t / WF_, wf = t - h * WF_;
        dR[t] = sR[h * PITCH + wf] * scale;
        dI[t] = sI[h * PITCH + wf] * scale;
    }
}

// ---------------------------------------------------------------------------
// Mixer: per (b,g) x 64-frequency tile: o2 = W2*relu(W1*X+b1)+b2 ; out = o2 (.) X
// Complex grouped GEMM in fp32.
// ---------------------------------------------------------------------------
__global__ void __launch_bounds__(256) kmix(const float* __restrict__ w1,
                                            const float* __restrict__ w2,
                                            const float* __restrict__ b1,
                                            const float* __restrict__ b2) {
    extern __shared__ float sm[];
    float* Xr  = sm;                  // 128*64
    float* Xi  = Xr  + D_ * TF_;
    float* O1r = Xi  + D_ * TF_;
    float* O1i = O1r + D_ * TF_;
    float* Wr  = O1i + D_ * TF_;      // 16*128
    float* Wi  = Wr  + 16 * D_;

    const int tid = threadIdx.x;
    const int ft  = blockIdx.x;       // 0..129
    const int bg  = blockIdx.y;       // 0..31
    const int b   = bg >> 2, g = bg & 3;

    const size_t xbase = ((size_t)b * C_ + (size_t)g * D_) * F_ + (size_t)ft * TF_;

    // Load X tile [128 ch x 64 freq]
    for (int t = tid * 4; t < D_ * TF_; t += 256 * 4) {
        int i = t >> 6, f = t & 63;
        *(float4*)&Xr[i * TF_ + f] = *(const float4*)&g_specR[xbase + (size_t)i * F_ + f];
        *(float4*)&Xi[i * TF_ + f] = *(const float4*)&g_specI[xbase + (size_t)i * F_ + f];
    }
    __syncthreads();

    const int tx = tid & 15, ty = tid >> 4;
    const int fo = tx * 4, oo = ty * 8;

    float aR[8][4], aI[8][4];

    // ================= Layer 1 =================
    #pragma unroll
    for (int j = 0; j < 8; j++)
        #pragma unroll
        for (int k = 0; k < 4; k++) { aR[j][k] = 0.0f; aI[j][k] = 0.0f; }

    const float* w1r = w1 + (size_t)g * D_ * D_;
    const float* w1i = w1 + (size_t)(G_ + g) * D_ * D_;

    for (int kc = 0; kc < D_; kc += 16) {
        for (int t = tid * 4; t < 16 * D_; t += 1024) {
            int i = t >> 7, o = t & 127;
            *(float4*)&Wr[t] = *(const float4*)&w1r[(size_t)(kc + i) * D_ + o];
            *(float4*)&Wi[t] = *(const float4*)&w1i[(size_t)(kc + i) * D_ + o];
        }
        __syncthreads();
        #pragma unroll
        for (int i = 0; i < 16; i++) {
            float4 fxr = *(float4*)&Xr[(kc + i) * TF_ + fo];
            float4 fxi = *(float4*)&Xi[(kc + i) * TF_ + fo];
            float xrv[4] = {fxr.x, fxr.y, fxr.z, fxr.w};
            float xiv[4] = {fxi.x, fxi.y, fxi.z, fxi.w};
            float wrv[8], wiv[8];
            *(float4*)&wrv[0] = *(float4*)&Wr[i * D_ + oo];
            *(float4*)&wrv[4] = *(float4*)&Wr[i * D_ + oo + 4];
            *(float4*)&wiv[0] = *(float4*)&Wi[i * D_ + oo];
            *(float4*)&wiv[4] = *(float4*)&Wi[i * D_ + oo + 4];
            #pragma unroll
            for (int j = 0; j < 8; j++) {
                float wr = wrv[j], wi_ = wiv[j];
                #pragma unroll
                for (int k = 0; k < 4; k++) {
                    aR[j][k] = fmaf(xrv[k], wr,  aR[j][k]);
                    aR[j][k] = fmaf(-xiv[k], wi_, aR[j][k]);
                    aI[j][k] = fmaf(xiv[k], wr,  aI[j][k]);
                    aI[j][k] = fmaf(xrv[k], wi_, aI[j][k]);
                }
            }
        }
        __syncthreads();
    }

    // bias + relu -> O1
    {
        const float* b1r = b1 + (size_t)g * D_;
        const float* b1i = b1 + (size_t)G_ * D_ + (size_t)g * D_;
        #pragma unroll
        for (int j = 0; j < 8; j++) {
            float brv = __ldg(&b1r[oo + j]);
            float biv = __ldg(&b1i[oo + j]);
            #pragma unroll
            for (int k = 0; k < 4; k++) {
                float vr = aR[j][k] + brv; vr = vr > 0.0f ? vr : 0.0f;
                float vi = aI[j][k] + biv; vi = vi > 0.0f ? vi : 0.0f;
                O1r[(oo + j) * TF_ + fo + k] = vr;
                O1i[(oo + j) * TF_ + fo + k] = vi;
            }
        }
    }
    __syncthreads();

    // ================= Layer 2 =================
    #pragma unroll
    for (int j = 0; j < 8; j++)
        #pragma unroll
        for (int k = 0; k < 4; k++) { aR[j][k] = 0.0f; aI[j][k] = 0.0f; }

    const float* w2r = w2 + (size_t)g * D_ * D_;
    const float* w2i = w2 + (size_t)(G_ + g) * D_ * D_;

    for (int kc = 0; kc < D_; kc += 16) {
        for (int t = tid * 4; t < 16 * D_; t += 1024) {
            int i = t >> 7, o = t & 127;
            *(float4*)&Wr[t] = *(const float4*)&w2r[(size_t)(kc + i) * D_ + o];
            *(float4*)&Wi[t] = *(const float4*)&w2i[(size_t)(kc + i) * D_ + o];
        }
        __syncthreads();
        #pragma unroll
        for (int i = 0; i < 16; i++) {
            float4 fxr = *(float4*)&O1r[(kc + i) * TF_ + fo];
            float4 fxi = *(float4*)&O1i[(kc + i) * TF_ + fo];
            float xrv[4] = {fxr.x, fxr.y, fxr.z, fxr.w};
            float xiv[4] = {fxi.x, fxi.y, fxi.z, fxi.w};
            float wrv[8], wiv[8];
            *(float4*)&wrv[0] = *(float4*)&Wr[i * D_ + oo];
            *(float4*)&wrv[4] = *(float4*)&Wr[i * D_ + oo + 4];
            *(float4*)&wiv[0] = *(float4*)&Wi[i * D_ + oo];
            *(float4*)&wiv[4] = *(float4*)&Wi[i * D_ + oo + 4];
            #pragma unroll
            for (int j = 0; j < 8; j++) {
                float wr = wrv[j], wi_ = wiv[j];
                #pragma unroll
                for (int k = 0; k < 4; k++) {
                    aR[j][k] = fmaf(xrv[k], wr,  aR[j][k]);
                    aR[j][k] = fmaf(-xiv[k], wi_, aR[j][k]);
                    aI[j][k] = fmaf(xiv[k], wr,  aI[j][k]);
                    aI[j][k] = fmaf(xrv[k], wi_, aI[j][k]);
                }
            }
        }
        __syncthreads();
    }

    // bias, multiply by origin, store
    {
        const float* b2r = b2 + (size_t)g * D_;
        const float* b2i = b2 + (size_t)G_ * D_ + (size_t)g * D_;
        #pragma unroll
        for (int j = 0; j < 8; j++) {
            float brv = __ldg(&b2r[oo + j]);
            float biv = __ldg(&b2i[oo + j]);
            float4 orv, oiv;
            float* orp = &orv.x;
            float* oip = &oiv.x;
            #pragma unroll
            for (int k = 0; k < 4; k++) {
                float vr = aR[j][k] + brv;
                float vi = aI[j][k] + biv;
                float xr = Xr[(oo + j) * TF_ + fo + k];
                float xi = Xi[(oo + j) * TF_ + fo + k];
                orp[k] = vr * xr - vi * xi;
                oip[k] = vr * xi + vi * xr;
            }
            size_t dst = ((size_t)b * C_ + (size_t)g * D_ + (oo + j)) * F_ + (size_t)ft * TF_ + fo;
            *(float4*)&g_outR[dst] = orv;
            *(float4*)&g_outI[dst] = oiv;
        }
    }
}

// ---------------------------------------------------------------------------
// Inverse: per (b,c): H-axis IFFT on 65 cols, Hermitian mirror per row,
// W-axis IFFT, take real part, scale 1/128.
// ---------------------------------------------------------------------------
__global__ void __launch_bounds__(256) kfft_inv(float* __restrict__ y) {
    extern __shared__ float sm[];
    float* sR  = sm;
    float* sI  = sR + 128 * PITCH;
    float* twR = sI + 128 * PITCH;
    float* twI = twR + 64;

    const int tid = threadIdx.x;
    const int img = blockIdx.x;

    if (tid < 64) {
        float s, c;
        sincospif(2.0f * (float)tid / 128.0f, &s, &c);   // exp(+2*pi*i*t/128)
        twR[tid] = c; twI[tid] = s;
    }

    // Load processed spectrum, bit-reverse rows (h) on the fly
    const float* srcR = g_outR + (size_t)img * F_;
    const float* srcI = g_outI + (size_t)img * F_;
    for (int t = tid; t < F_; t += 256) {
        int h = t / WF_, wf = t - h * WF_;
        int hb = __brev((unsigned)h) >> 25;
        sR[hb * PITCH + wf] = srcR[t];
        sI[hb * PITCH + wf] = srcI[t];
    }
    __syncthreads();

    // Column IFFTs (along h) on 65 columns
    for (int s = 1; s <= 7; s++) {
        int half = 1 << (s - 1);
        for (int t = tid; t < WF_ * 64; t += 256) {
            int c = t % WF_, bf = t / WF_;
            int j = bf & (half - 1);
            int base = (bf >> (s - 1)) << s;
            int i1 = (base + j) * PITCH + c;
            int i2 = i1 + half * PITCH;
            int ti_ = j << (7 - s);
            float wr = twR[ti_], wi = twI[ti_];
            float ar = sR[i1], ai = sI[i1];
            float br = sR[i2], bi = sI[i2];
            float tr = br * wr - bi * wi;
            float tq = br * wi + bi * wr;
            sR[i1] = ar + tr; sI[i1] = ai + tq;
            sR[i2] = ar - tr; sI[i2] = ai - tq;
        }
        __syncthreads();
    }

    // Hermitian mirror per row: w in 65..127 <- conj of 128-w
    for (int t = tid; t < 128 * 63; t += 256) {
        int r = t / 63, k = t - r * 63;
        int w = 65 + k;                 // 65..127
        int ws = 128 - w;               // 1..63
        sR[r * PITCH + w] =  sR[r * PITCH + ws];
        sI[r * PITCH + w] = -sI[r * PITCH + ws];
    }
    __syncthreads();

    // Bit-reverse columns (w) in-place
    for (int t = tid; t < 128 * 128; t += 256) {
        int r = t >> 7, c = t & 127;
        int cb = __brev((unsigned)c) >> 25;
        if (cb > c) {
            float a;
            a = sR[r * PITCH + c]; sR[r * PITCH + c] = sR[r * PITCH + cb]; sR[r * PITCH + cb] = a;
            a = sI[r * PITCH + c]; sI[r * PITCH + c] = sI[r * PITCH + cb]; sI[r * PITCH + cb] = a;
        }
    }
    __syncthreads();

    // Row IFFTs (along w), 128 rows
    for (int s = 1; s <= 7; s++) {
        int half = 1 << (s - 1);
        for (int t = tid; t < 128 * 64; t += 256) {
            int r = t >> 6, bf = t & 63;
            int j = bf & (half - 1);
            int base = (bf >> (s - 1)) << s;
            int i1 = r * PITCH + base + j;
            int i2 = i1 + half;
            int ti_ = j << (7 - s);
            float wr = twR[ti_], wi = twI[ti_];
            float ar = sR[i1], ai = sI[i1];
            float br = sR[i2], bi = sI[i2];
            float tr = br * wr - bi * wi;
            float tq = br * wi + bi * wr;
            sR[i1] = ar + tr; sI[i1] = ai + tq;
            sR[i2] = ar - tr; sI[i2] = ai - tq;
        }
        __syncthreads();
    }

    // Real part, ortho scale
    float* dst = y + (size_t)img * (H_ * W_);
    const float scale = 1.0f / 128.0f;
    for (int t = tid; t < H_ * W_; t += 256) {
        int r = t >> 7, c = t & 127;
        dst[t] = sR[r * PITCH + c] * scale;
    }
}

// ---------------------------------------------------------------------------
extern "C" void kernel_launch(void* const* d_in, const int* in_sizes, int n_in,
                              void* d_out, int out_size) {
    const float* x  = (const float*)d_in[0];
    const float* w1 = (const float*)d_in[1];
    const float* w2 = (const float*)d_in[2];
    const float* b1 = (const float*)d_in[3];
    const float* b2 = (const float*)d_in[4];
    float* y = (float*)d_out;

    const int smFFT = (2 * 128 * PITCH + 2 * 64) * (int)sizeof(float);   // ~132.6 KB
    const int smMIX = (4 * D_ * TF_ + 2 * 16 * D_) * (int)sizeof(float); // 144 KB

    cudaFuncSetAttribute(kfft_fwd, cudaFuncAttributeMaxDynamicSharedMemorySize, smFFT);
    cudaFuncSetAttribute(kmix,     cudaFuncAttributeMaxDynamicSharedMemorySize, smMIX);
    cudaFuncSetAttribute(kfft_inv, cudaFuncAttributeMaxDynamicSharedMemorySize, smFFT);

    kfft_fwd<<<NIMG, 256, smFFT>>>(x);
    kmix<<<dim3(F_ / TF_, B_ * G_), 256, smMIX>>>(w1, w2, b1, b2);
    kfft_inv<<<NIMG, 256, smFFT>>>(y);
}

// round 2
// speedup vs baseline: 1.7149x; 1.7149x over previous
#include <cuda_runtime.h>
#include <math.h>

#define B_   8
#define C_   512
#define G_   4
#define D_   128
#define H_   128
#define W_   128
#define WF_  65
#define F_   (H_*WF_)        // 8320
#define NIMG (B_*C_)         // 4096
#define TF_  64

// Scratch (allocation-free requirement -> device globals). ~545MB total.
static __device__ float g_specR[(size_t)NIMG * F_];
static __device__ float g_specI[(size_t)NIMG * F_];
static __device__ float g_outR [(size_t)NIMG * F_];
static __device__ float g_outI [(size_t)NIMG * F_];

#define RPIT 129   // packed-row buffer pitch (64 rows x 128 complex)
#define CPIT 65    // column buffer pitch (128 rows x 65 complex)
#define UBUF 8320  // max(64*129=8256, 128*65=8320) floats per plane
#define NT_F 512

__device__ __forceinline__ int brev7(int v) { return (int)(__brev((unsigned)v) >> 25); }

// ---------------------------------------------------------------------------
// Radix-4 (fused radix-2 stage pair S, S+1) over 64 rows, stride-1 sequences,
// pitch RPIT. Input in bit-reversed order, DIT.
// ---------------------------------------------------------------------------
template<int S>
__device__ __forceinline__ void pass4_rows(float* R, float* I,
                                           const float* twR, const float* twI) {
    const int h = 1 << (S - 1);
    for (int it = threadIdx.x; it < 64 * 32; it += NT_F) {
        int r = it & 63, q = it >> 6;
        int j = q & (h - 1);
        int base = (q >> (S - 1)) << (S + 1);
        int i0 = r * RPIT + base + j;
        float e0r = R[i0],       e0i = I[i0];
        float e1r = R[i0 + h],   e1i = I[i0 + h];
        float e2r = R[i0 + 2*h], e2i = I[i0 + 2*h];
        float e3r = R[i0 + 3*h], e3i = I[i0 + 3*h];
        float w1r = twR[j << (7-S)], w1i = twI[j << (7-S)];
        float w2r = twR[j << (6-S)], w2i = twI[j << (6-S)];
        float w3r = twR[(j+h) << (6-S)], w3i = twI[(j+h) << (6-S)];
        float tr = e1r*w1r - e1i*w1i, ti = e1r*w1i + e1i*w1r;
        float A0r = e0r + tr, A0i = e0i + ti, A1r = e0r - tr, A1i = e0i - ti;
        tr = e3r*w1r - e3i*w1i; ti = e3r*w1i + e3i*w1r;
        float A2r = e2r + tr, A2i = e2i + ti, A3r = e2r - tr, A3i = e2i - ti;
        tr = A2r*w2r - A2i*w2i; ti = A2r*w2i + A2i*w2r;
        R[i0]       = A0r + tr; I[i0]       = A0i + ti;
        R[i0 + 2*h] = A0r - tr; I[i0 + 2*h] = A0i - ti;
        tr = A3r*w3r - A3i*w3i; ti = A3r*w3i + A3i*w3r;
        R[i0 + h]   = A1r + tr; I[i0 + h]   = A1i + ti;
        R[i0 + 3*h] = A1r - tr; I[i0 + 3*h] = A1i - ti;
    }
}

__device__ __forceinline__ void pass2_rows(float* R, float* I,
                                           const float* twR, const float* twI) {
    for (int it = threadIdx.x; it < 64 * 64; it += NT_F) {
        int r = it & 63, j = it >> 6;
        int i0 = r * RPIT + j, i1 = i0 + 64;
        float wr = twR[j], wi = twI[j];
        float ar = R[i0], ai = I[i0], br = R[i1], bi = I[i1];
        float tr = br*wr - bi*wi, ti = br*wi + bi*wr;
        R[i0] = ar + tr; I[i0] = ai + ti;
        R[i1] = ar - tr; I[i1] = ai - ti;
    }
}

// Same, over 65 columns, stride-CPIT sequences of length 128.
template<int S>
__device__ __forceinline__ void pass4_cols(float* R, float* I,
                                           const float* twR, const float* twI) {
    const int h = 1 << (S - 1);
    const int st = h * CPIT;
    for (int it = threadIdx.x; it < 65 * 32; it += NT_F) {
        int c = it % 65, q = it / 65;
        int j = q & (h - 1);
        int base = (q >> (S - 1)) << (S + 1);
        int i0 = (base + j) * CPIT + c;
        float e0r = R[i0],        e0i = I[i0];
        float e1r = R[i0 + st],   e1i = I[i0 + st];
        float e2r = R[i0 + 2*st], e2i = I[i0 + 2*st];
        float e3r = R[i0 + 3*st], e3i = I[i0 + 3*st];
        float w1r = twR[j << (7-S)], w1i = twI[j << (7-S)];
        float w2r = twR[j << (6-S)], w2i = twI[j << (6-S)];
        float w3r = twR[(j+h) << (6-S)], w3i = twI[(j+h) << (6-S)];
        float tr = e1r*w1r - e1i*w1i, ti = e1r*w1i + e1i*w1r;
        float A0r = e0r + tr, A0i = e0i + ti, A1r = e0r - tr, A1i = e0i - ti;
        tr = e3r*w1r - e3i*w1i; ti = e3r*w1i + e3i*w1r;
        float A2r = e2r + tr, A2i = e2i + ti, A3r = e2r - tr, A3i = e2i - ti;
        tr = A2r*w2r - A2i*w2i; ti = A2r*w2i + A2i*w2r;
        R[i0]        = A0r + tr; I[i0]        = A0i + ti;
        R[i0 + 2*st] = A0r - tr; I[i0 + 2*st] = A0i - ti;
        tr = A3r*w3r - A3i*w3i; ti = A3r*w3i + A3i*w3r;
        R[i0 + st]   = A1r + tr; I[i0 + st]   = A1i + ti;
        R[i0 + 3*st] = A1r - tr; I[i0 + 3*st] = A1i - ti;
    }
}

__device__ __forceinline__ void pass2_cols(float* R, float* I,
                                           const float* twR, const float* twI) {
    for (int it = threadIdx.x; it < 65 * 64; it += NT_F) {
        int c = it % 65, j = it / 65;
        int i0 = j * CPIT + c, i1 = i0 + 64 * CPIT;
        float wr = twR[j], wi = twI[j];
        float ar = R[i0], ai = I[i0], br = R[i1], bi = I[i1];
        float tr = br*wr - bi*wi, ti = br*wi + bi*wr;
        R[i0] = ar + tr; I[i0] = ai + ti;
        R[i1] = ar - tr; I[i1] = ai - ti;
    }
}

// ---------------------------------------------------------------------------
// Forward: two-for-one packed real row FFTs (64 complex FFTs for 128 real
// rows), unpack to half-spectrum (register-staged, aliased buffer), column
// FFTs on 65 cols. Ortho scale 1/128.
// ---------------------------------------------------------------------------
__global__ void __launch_bounds__(NT_F, 2) kfft_fwd(const float* __restrict__ x) {
    extern __shared__ float sm[];
    float* R   = sm;
    float* I   = sm + UBUF;
    float* twR = sm + 2 * UBUF;
    float* twI = twR + 64;

    const int tid = threadIdx.x;
    const int img = blockIdx.x;

    if (tid < 64) {
        float s, c;
        sincospif(-(float)tid / 64.0f, &s, &c);   // exp(-2*pi*i*t/128)
        twR[tid] = c; twI[tid] = s;
    }

    // Load: pack rows (2p, 2p+1) as complex, bit-reverse w on the fly
    const float* src = x + (size_t)img * (H_ * W_);
    for (int t = tid; t < 64 * 128; t += NT_F) {
        int p = t >> 7, c = t & 127;
        int cb = brev7(c);
        R[p * RPIT + cb] = src[(2 * p) * 128 + c];
        I[p * RPIT + cb] = src[(2 * p) * 128 + 128 + c];
    }
    __syncthreads();

    pass4_rows<1>(R, I, twR, twI); __syncthreads();
    pass4_rows<3>(R, I, twR, twI); __syncthreads();
    pass4_rows<5>(R, I, twR, twI); __syncthreads();
    pass2_rows   (R, I, twR, twI); __syncthreads();

    // Unpack two-for-one: X0[k]=(Z[k]+conj(Z[m]))/2, X1[k]=((Zi[k]+Zi[m])/2, (Zr[m]-Zr[k])/2)
    // Register-staged so dest (column layout) can alias source (packed layout).
    float u0r[9], u0i[9], u1r[9], u1i[9];
    #pragma unroll
    for (int n = 0; n < 9; n++) {
        int it = tid + n * NT_F;
        if (it < 64 * 65) {
            int k = it % 65, p = it / 65;
            int m = (128 - k) & 127;
            float a = R[p * RPIT + k], b = I[p * RPIT + k];
            float c2 = R[p * RPIT + m], d = I[p * RPIT + m];
            u0r[n] = 0.5f * (a + c2); u0i[n] = 0.5f * (b - d);
            u1r[n] = 0.5f * (b + d);  u1i[n] = 0.5f * (c2 - a);
        }
    }
    __syncthreads();
    #pragma unroll
    for (int n = 0; n < 9; n++) {
        int it = tid + n * NT_F;
        if (it < 64 * 65) {
            int k = it % 65, p = it / 65;
            int h0 = brev7(2 * p), h1 = brev7(2 * p + 1);  // pre-reverse h for col FFT
            R[h0 * CPIT + k] = u0r[n]; I[h0 * CPIT + k] = u0i[n];
            R[h1 * CPIT + k] = u1r[n]; I[h1 * CPIT + k] = u1i[n];
        }
    }
    __syncthreads();

    pass4_cols<1>(R, I, twR, twI); __syncthreads();
    pass4_cols<3>(R, I, twR, twI); __syncthreads();
    pass4_cols<5>(R, I, twR, twI); __syncthreads();
    pass2_cols   (R, I, twR, twI); __syncthreads();

    // Store (buffer index == h*65+k == t since CPIT==65)
    float* dR = g_specR + (size_t)img * F_;
    float* dI = g_specI + (size_t)img * F_;
    const float sc = 1.0f / 128.0f;
    for (int t = tid; t < F_; t += NT_F) {
        dR[t] = R[t] * sc;
        dI[t] = I[t] * sc;
    }
}

// ---------------------------------------------------------------------------
// Mixer: o2 = W2*relu(W1*X+b1)+b2 ; out = o2 (.) X
// Karatsuba complex GEMM: P1=Xr*Wr, P2=Xi*Wi, P3=(Xr+Xi)*(Wr+Wi)
// Or=P1-P2, Oi=P3-P1-P2  (3 real GEMMs instead of 4).
// ---------------------------------------------------------------------------
__global__ void __launch_bounds__(256) kmix(const float* __restrict__ w1,
                                            const float* __restrict__ w2,
                                            const float* __restrict__ b1,
                                            const float* __restrict__ b2) {
    extern __shared__ float sm[];
    float* Xr  = sm;               // 128*64
    float* Xi  = Xr  + 8192;
    float* Xs  = Xi  + 8192;
    float* O1r = Xs  + 8192;
    float* O1i = O1r + 8192;
    float* O1s = O1i + 8192;
    float* Wr  = O1s + 8192;       // 16*128
    float* Wi  = Wr  + 2048;
    float* Ws  = Wi  + 2048;

    const int tid = threadIdx.x;
    const int ft  = blockIdx.x;       // 0..129
    const int bg  = blockIdx.y;       // 0..31
    const int b   = bg >> 2, g = bg & 3;

    const size_t xbase = ((size_t)b * C_ + (size_t)g * D_) * F_ + (size_t)ft * TF_;

    // Load X tile [128 ch x 64 freq] + sum plane
    for (int t = tid * 4; t < D_ * TF_; t += 256 * 4) {
        int i = t >> 6, f = t & 63;
        float4 vr = *(const float4*)&g_specR[xbase + (size_t)i * F_ + f];
        float4 vi = *(const float4*)&g_specI[xbase + (size_t)i * F_ + f];
        *(float4*)&Xr[t] = vr;
        *(float4*)&Xi[t] = vi;
        *(float4*)&Xs[t] = make_float4(vr.x+vi.x, vr.y+vi.y, vr.z+vi.z, vr.w+vi.w);
    }
    __syncthreads();

    const int tx = tid & 15, ty = tid >> 4;
    const int fo = tx * 4, oo = ty * 8;

    float p1[8][4], p2[8][4], p3[8][4];

    // ================= Layer 1 =================
    #pragma unroll
    for (int j = 0; j < 8; j++)
        #pragma unroll
        for (int k = 0; k < 4; k++) { p1[j][k] = 0.f; p2[j][k] = 0.f; p3[j][k] = 0.f; }

    const float* w1r = w1 + (size_t)g * D_ * D_;
    const float* w1i = w1 + (size_t)(G_ + g) * D_ * D_;

    for (int kc = 0; kc < D_; kc += 16) {
        for (int t = tid * 4; t < 16 * D_; t += 1024) {
            int i = t >> 7, o = t & 127;
            float4 a = *(const float4*)&w1r[(size_t)(kc + i) * D_ + o];
            float4 c = *(const float4*)&w1i[(size_t)(kc + i) * D_ + o];
            *(float4*)&Wr[t] = a;
            *(float4*)&Wi[t] = c;
            *(float4*)&Ws[t] = make_float4(a.x+c.x, a.y+c.y, a.z+c.z, a.w+c.w);
        }
        __syncthreads();
        #pragma unroll
        for (int i = 0; i < 16; i++) {
            float4 fxr = *(float4*)&Xr[(kc + i) * TF_ + fo];
            float4 fxi = *(float4*)&Xi[(kc + i) * TF_ + fo];
            float4 fxs = *(float4*)&Xs[(kc + i) * TF_ + fo];
            float xr[4] = {fxr.x, fxr.y, fxr.z, fxr.w};
            float xv[4] = {fxi.x, fxi.y, fxi.z, fxi.w};
            float xs[4] = {fxs.x, fxs.y, fxs.z, fxs.w};
            float wr[8], wv[8], ws[8];
            *(float4*)&wr[0] = *(float4*)&Wr[i * D_ + oo];
            *(float4*)&wr[4] = *(float4*)&Wr[i * D_ + oo + 4];
            *(float4*)&wv[0] = *(float4*)&Wi[i * D_ + oo];
            *(float4*)&wv[4] = *(float4*)&Wi[i * D_ + oo + 4];
            *(float4*)&ws[0] = *(float4*)&Ws[i * D_ + oo];
            *(float4*)&ws[4] = *(float4*)&Ws[i * D_ + oo + 4];
            #pragma unroll
            for (int j = 0; j < 8; j++) {
                #pragma unroll
                for (int k = 0; k < 4; k++) {
                    p1[j][k] = fmaf(xr[k], wr[j], p1[j][k]);
                    p2[j][k] = fmaf(xv[k], wv[j], p2[j][k]);
                    p3[j][k] = fmaf(xs[k], ws[j], p3[j][k]);
                }
            }
        }
        __syncthreads();
    }

    // bias + relu -> O1 (+ sum plane)
    {
        const float* b1r = b1 + (size_t)g * D_;
        const float* b1i = b1 + (size_t)G_ * D_ + (size_t)g * D_;
        #pragma unroll
        for (int j = 0; j < 8; j++) {
            float brv = __ldg(&b1r[oo + j]);
            float biv = __ldg(&b1i[oo + j]);
            float4 r4, i4, s4;
            float* rp = &r4.x; float* ip = &i4.x; float* sp = &s4.x;
            #pragma unroll
            for (int k = 0; k < 4; k++) {
                float vr = p1[j][k] - p2[j][k] + brv;
                float vi = p3[j][k] - p1[j][k] - p2[j][k] + biv;
                vr = vr > 0.f ? vr : 0.f;
                vi = vi > 0.f ? vi : 0.f;
                rp[k] = vr; ip[k] = vi; sp[k] = vr + vi;
            }
            int o = (oo + j) * TF_ + fo;
            *(float4*)&O1r[o] = r4;
            *(float4*)&O1i[o] = i4;
            *(float4*)&O1s[o] = s4;
        }
    }
    __syncthreads();

    // ================= Layer 2 =================
    #pragma unroll
    for (int j = 0; j < 8; j++)
        #pragma unroll
        for (int k = 0; k < 4; k++) { p1[j][k] = 0.f; p2[j][k] = 0.f; p3[j][k] = 0.f; }

    const float* w2r = w2 + (size_t)g * D_ * D_;
    const float* w2i = w2 + (size_t)(G_ + g) * D_ * D_;

    for (int kc = 0; kc < D_; kc += 16) {
        for (int t = tid * 4; t < 16 * D_; t += 1024) {
            int i = t >> 7, o = t & 127;
            float4 a = *(const float4*)&w2r[(size_t)(kc + i) * D_ + o];
            float4 c = *(const float4*)&w2i[(size_t)(kc + i) * D_ + o];
            *(float4*)&Wr[t] = a;
            *(float4*)&Wi[t] = c;
            *(float4*)&Ws[t] = make_float4(a.x+c.x, a.y+c.y, a.z+c.z, a.w+c.w);
        }
        __syncthreads();
        #pragma unroll
        for (int i = 0; i < 16; i++) {
            float4 fxr = *(float4*)&O1r[(kc + i) * TF_ + fo];
            float4 fxi = *(float4*)&O1i[(kc + i) * TF_ + fo];
            float4 fxs = *(float4*)&O1s[(kc + i) * TF_ + fo];
            float xr[4] = {fxr.x, fxr.y, fxr.z, fxr.w};
            float xv[4] = {fxi.x, fxi.y, fxi.z, fxi.w};
            float xs[4] = {fxs.x, fxs.y, fxs.z, fxs.w};
            float wr[8], wv[8], ws[8];
            *(float4*)&wr[0] = *(float4*)&Wr[i * D_ + oo];
            *(float4*)&wr[4] = *(float4*)&Wr[i * D_ + oo + 4];
            *(float4*)&wv[0] = *(float4*)&Wi[i * D_ + oo];
            *(float4*)&wv[4] = *(float4*)&Wi[i * D_ + oo + 4];
            *(float4*)&ws[0] = *(float4*)&Ws[i * D_ + oo];
            *(float4*)&ws[4] = *(float4*)&Ws[i * D_ + oo + 4];
            #pragma unroll
            for (int j = 0; j < 8; j++) {
                #pragma unroll
                for (int k = 0; k < 4; k++) {
                    p1[j][k] = fmaf(xr[k], wr[j], p1[j][k]);
                    p2[j][k] = fmaf(xv[k], wv[j], p2[j][k]);
                    p3[j][k] = fmaf(xs[k], ws[j], p3[j][k]);
                }
            }
        }
        __syncthreads();
    }

    // bias, multiply by origin, store
    {
        const float* b2r = b2 + (size_t)g * D_;
        const float* b2i = b2 + (size_t)G_ * D_ + (size_t)g * D_;
        #pragma unroll
        for (int j = 0; j < 8; j++) {
            float brv = __ldg(&b2r[oo + j]);
            float biv = __ldg(&b2i[oo + j]);
            float4 orv, oiv;
            float* orp = &orv.x;
            float* oip = &oiv.x;
            #pragma unroll
            for (int k = 0; k < 4; k++) {
                float vr = p1[j][k] - p2[j][k] + brv;
                float vi = p3[j][k] - p1[j][k] - p2[j][k] + biv;
                float xr = Xr[(oo + j) * TF_ + fo + k];
                float xi = Xi[(oo + j) * TF_ + fo + k];
                orp[k] = vr * xr - vi * xi;
                oip[k] = vr * xi + vi * xr;
            }
            size_t dst = ((size_t)b * C_ + (size_t)g * D_ + (oo + j)) * F_ + (size_t)ft * TF_ + fo;
            *(float4*)&g_outR[dst] = orv;
            *(float4*)&g_outI[dst] = oiv;
        }
    }
}

// ---------------------------------------------------------------------------
// Inverse: column IFFTs on 65 cols, two-for-one packed inverse row transform
// (build Hermitian Z = X0 + i*X1 per row pair, one complex IFFT per pair,
// real/imag = the two rows). Imag of bins 0/64 zeroed == irfft semantics.
// ---------------------------------------------------------------------------
__global__ void __launch_bounds__(NT_F, 2) kfft_inv(float* __restrict__ y) {
    extern __shared__ float sm[];
    float* R   = sm;
    float* I   = sm + UBUF;
    float* twR = sm + 2 * UBUF;
    float* twI = twR + 64;

    const int tid = threadIdx.x;
    const int img = blockIdx.x;

    if (tid < 64) {
        float s, c;
        sincospif((float)tid / 64.0f, &s, &c);    // exp(+2*pi*i*t/128)
        twR[tid] = c; twI[tid] = s;
    }

    // Load processed spectrum, bit-reverse h on the fly (column layout)
    const float* srcR = g_outR + (size_t)img * F_;
    const float* srcI = g_outI + (size_t)img * F_;
    for (int t = tid; t < F_; t += NT_F) {
        int h = t / WF_, k = t - h * WF_;
        int hb = brev7(h);
        R[hb * CPIT + k] = srcR[t];
        I[hb * CPIT + k] = srcI[t];
    }
    __syncthreads();

    pass4_cols<1>(R, I, twR, twI); __syncthreads();
    pass4_cols<3>(R, I, twR, twI); __syncthreads();
    pass4_cols<5>(R, I, twR, twI); __syncthreads();
    pass2_cols   (R, I, twR, twI); __syncthreads();

    // Pack row pairs: Z[w] = X0[w] + i*X1[w] with Hermitian extension.
    // Register-staged (dest packed layout aliases source column layout).
    float zr[16], zi[16];
    #pragma unroll
    for (int n = 0; n < 16; n++) {
        int it = tid + n * NT_F;         // 16*512 = 8192 exact
        int w = it & 127, p = it >> 7;
        int r0 = (2 * p) * CPIT, r1 = r0 + CPIT;
        if (w <= 64) {
            float x0r = R[r0 + w], x0i = I[r0 + w];
            float x1r = R[r1 + w], x1i = I[r1 + w];
            if (w == 0 || w == 64) { x0i = 0.f; x1i = 0.f; }  // irfft ignores these
            zr[n] = x0r - x1i;
            zi[n] = x0i + x1r;
        } else {
            int m = 128 - w;
            float x0r = R[r0 + m], x0i = I[r0 + m];
            float x1r = R[r1 + m], x1i = I[r1 + m];
            zr[n] = x0r + x1i;
            zi[n] = x1r - x0i;
        }
    }
    __syncthreads();
    #pragma unroll
    for (int n = 0; n < 16; n++) {
        int it = tid + n * NT_F;
        int w = it & 127, p = it >> 7;
        int wb = brev7(w);
        R[p * RPIT + wb] = zr[n];
        I[p * RPIT + wb] = zi[n];
    }
    __syncthreads();

    pass4_rows<1>(R, I, twR, twI); __syncthreads();
    pass4_rows<3>(R, I, twR, twI); __syncthreads();
    pass4_rows<5>(R, I, twR, twI); __syncthreads();
    pass2_rows   (R, I, twR, twI); __syncthreads();

    // Real = row 2p, Imag = row 2p+1; ortho scale 1/128
    float* dst = y + (size_t)img * (H_ * W_);
    const float sc = 1.0f / 128.0f;
    for (int t = tid; t < 64 * 128; t += NT_F) {
        int p = t >> 7, c = t & 127;
        dst[(2 * p) * 128 + c]       = R[p * RPIT + c] * sc;
        dst[(2 * p) * 128 + 128 + c] = I[p * RPIT + c] * sc;
    }
}

// ---------------------------------------------------------------------------
extern "C" void kernel_launch(void* const* d_in, const int* in_sizes, int n_in,
                              void* d_out, int out_size) {
    const float* x  = (const float*)d_in[0];
    const float* w1 = (const float*)d_in[1];
    const float* w2 = (const float*)d_in[2];
    const float* b1 = (const float*)d_in[3];
    const float* b2 = (const float*)d_in[4];
    float* y = (float*)d_out;

    const int smFFT = (2 * UBUF + 128) * (int)sizeof(float);                    // ~65.5 KB
    const int smMIX = (6 * D_ * TF_ + 3 * 16 * D_) * (int)sizeof(float);        // 216 KB

    cudaFuncSetAttribute(kfft_fwd, cudaFuncAttributeMaxDynamicSharedMemorySize, smFFT);
    cudaFuncSetAttribute(kmix,     cudaFuncAttributeMaxDynamicSharedMemorySize, smMIX);
    cudaFuncSetAttribute(kfft_inv, cudaFuncAttributeMaxDynamicSharedMemorySize, smFFT);

    kfft_fwd<<<NIMG, NT_F, smFFT>>>(x);
    kmix<<<dim3(F_ / TF_, B_ * G_), 256, smMIX>>>(w1, w2, b1, b2);
    kfft_inv<<<NIMG, NT_F, smFFT>>>(y);
}

// round 4
// speedup vs baseline: 2.3627x; 1.3777x over previous
#include <cuda_runtime.h>
#include <cuda_bf16.h>
#include <math.h>
#include <stdint.h>

#define B_   8
#define C_   512
#define G_   4
#define D_   128
#define H_   128
#define W_   128
#define WF_  65
#define F_   (H_*WF_)        // 8320
#define NIMG (B_*C_)         // 4096

// Scratch (allocation-free requirement -> device globals).
static __device__ float g_specR[(size_t)NIMG * F_];
static __device__ float g_specI[(size_t)NIMG * F_];
static __device__ float g_outR [(size_t)NIMG * F_];
static __device__ float g_outI [(size_t)NIMG * F_];
static __device__ unsigned short g_wimg[32 * 128 * 136];  // 32 planes, pitch-136 bf16

#define RPIT 129
#define CPIT 65
#define UBUF 8320
#define NT_F 512

#define WP   136            // bf16 plane pitch (conflict-free: 68 words % 32 == 4)
#define PLW  (128 * WP)     // W plane elems (17408)
#define PLX  (64 * WP)      // X plane elems (8704)

__device__ __forceinline__ int brev7(int v) { return (int)(__brev((unsigned)v) >> 25); }

__device__ __forceinline__ void split_bf16(float v, unsigned short& h, unsigned short& l) {
    __nv_bfloat16 hb = __float2bfloat16(v);
    float r = v - __bfloat162float(hb);
    h = __bfloat16_as_ushort(hb);
    l = __bfloat16_as_ushort(__float2bfloat16(r));
}

// ---------------------------------------------------------------------------
// Weight prep: pre-split bf16 hi/lo planes, layout A[m=out][k=in], pitch WP.
// Plane id = (l*4+g)*4 + pl, pl: 0=rH 1=rL 2=iH 3=iL.
// ---------------------------------------------------------------------------
__global__ void __launch_bounds__(256) wprep(const float* __restrict__ w1,
                                             const float* __restrict__ w2) {
    int idx = blockIdx.x * 256 + threadIdx.x;      // 262144
    int m    = idx & 127;
    int k    = (idx >> 7) & 127;
    int part = (idx >> 14) & 1;
    int g    = (idx >> 15) & 3;
    int l    = (idx >> 17) & 1;
    const float* src = l ? w2 : w1;
    float v = src[(((size_t)(part * 4 + g) * 128 + k) * 128) + m];
    unsigned short h, lo;
    split_bf16(v, h, lo);
    size_t base = (size_t)((l * 4 + g) * 4 + part * 2) * PLW;
    g_wimg[base + m * WP + k]       = h;
    g_wimg[base + PLW + m * WP + k] = lo;
}

// ============================ FFT passes (unchanged) ========================
template<int S>
__device__ __forceinline__ void pass4_rows(float* R, float* I,
                                           const float* twR, const float* twI) {
    const int h = 1 << (S - 1);
    for (int it = threadIdx.x; it < 64 * 32; it += NT_F) {
        int r = it & 63, q = it >> 6;
        int j = q & (h - 1);
        int base = (q >> (S - 1)) << (S + 1);
        int i0 = r * RPIT + base + j;
        float e0r = R[i0],       e0i = I[i0];
        float e1r = R[i0 + h],   e1i = I[i0 + h];
        float e2r = R[i0 + 2*h], e2i = I[i0 + 2*h];
        float e3r = R[i0 + 3*h], e3i = I[i0 + 3*h];
        float w1r = twR[j << (7-S)], w1i = twI[j << (7-S)];
        float w2r = twR[j << (6-S)], w2i = twI[j << (6-S)];
        float w3r = twR[(j+h) << (6-S)], w3i = twI[(j+h) << (6-S)];
        float tr = e1r*w1r - e1i*w1i, ti = e1r*w1i + e1i*w1r;
        float A0r = e0r + tr, A0i = e0i + ti, A1r = e0r - tr, A1i = e0i - ti;
        tr = e3r*w1r - e3i*w1i; ti = e3r*w1i + e3i*w1r;
        float A2r = e2r + tr, A2i = e2i + ti, A3r = e2r - tr, A3i = e2i - ti;
        tr = A2r*w2r - A2i*w2i; ti = A2r*w2i + A2i*w2r;
        R[i0]       = A0r + tr; I[i0]       = A0i + ti;
        R[i0 + 2*h] = A0r - tr; I[i0 + 2*h] = A0i - ti;
        tr = A3r*w3r - A3i*w3i; ti = A3r*w3i + A3i*w3r;
        R[i0 + h]   = A1r + tr; I[i0 + h]   = A1i + ti;
        R[i0 + 3*h] = A1r - tr; I[i0 + 3*h] = A1i - ti;
    }
}

__device__ __forceinline__ void pass2_rows(float* R, float* I,
                                           const float* twR, const float* twI) {
    for (int it = threadIdx.x; it < 64 * 64; it += NT_F) {
        int r = it & 63, j = it >> 6;
        int i0 = r * RPIT + j, i1 = i0 + 64;
        float wr = twR[j], wi = twI[j];
        float ar = R[i0], ai = I[i0], br = R[i1], bi = I[i1];
        float tr = br*wr - bi*wi, ti = br*wi + bi*wr;
        R[i0] = ar + tr; I[i0] = ai + ti;
        R[i1] = ar - tr; I[i1] = ai - ti;
    }
}

template<int S>
__device__ __forceinline__ void pass4_cols(float* R, float* I,
                                           const float* twR, const float* twI) {
    const int h = 1 << (S - 1);
    const int st = h * CPIT;
    for (int it = threadIdx.x; it < 65 * 32; it += NT_F) {
        int c = it % 65, q = it / 65;
        int j = q & (h - 1);
        int base = (q >> (S - 1)) << (S + 1);
        int i0 = (base + j) * CPIT + c;
        float e0r = R[i0],        e0i = I[i0];
        float e1r = R[i0 + st],   e1i = I[i0 + st];
        float e2r = R[i0 + 2*st], e2i = I[i0 + 2*st];
        float e3r = R[i0 + 3*st], e3i = I[i0 + 3*st];
        float w1r = twR[j << (7-S)], w1i = twI[j << (7-S)];
        float w2r = twR[j << (6-S)], w2i = twI[j << (6-S)];
        float w3r = twR[(j+h) << (6-S)], w3i = twI[(j+h) << (6-S)];
        float tr = e1r*w1r - e1i*w1i, ti = e1r*w1i + e1i*w1r;
        float A0r = e0r + tr, A0i = e0i + ti, A1r = e0r - tr, A1i = e0i - ti;
        tr = e3r*w1r - e3i*w1i; ti = e3r*w1i + e3i*w1r;
        float A2r = e2r + tr, A2i = e2i + ti, A3r = e2r - tr, A3i = e2i - ti;
        tr = A2r*w2r - A2i*w2i; ti = A2r*w2i + A2i*w2r;
        R[i0]        = A0r + tr; I[i0]        = A0i + ti;
        R[i0 + 2*st] = A0r - tr; I[i0 + 2*st] = A0i - ti;
        tr = A3r*w3r - A3i*w3i; ti = A3r*w3i + A3i*w3r;
        R[i0 + st]   = A1r + tr; I[i0 + st]   = A1i + ti;
        R[i0 + 3*st] = A1r - tr; I[i0 + 3*st] = A1i - ti;
    }
}

__device__ __forceinline__ void pass2_cols(float* R, float* I,
                                           const float* twR, const float* twI) {
    for (int it = threadIdx.x; it < 65 * 64; it += NT_F) {
        int c = it % 65, j = it / 65;
        int i0 = j * CPIT + c, i1 = i0 + 64 * CPIT;
        float wr = twR[j], wi = twI[j];
        float ar = R[i0], ai = I[i0], br = R[i1], bi = I[i1];
        float tr = br*wr - bi*wi, ti = br*wi + bi*wr;
        R[i0] = ar + tr; I[i0] = ai + ti;
        R[i1] = ar - tr; I[i1] = ai - ti;
    }
}

__global__ void __launch_bounds__(NT_F, 2) kfft_fwd(const float* __restrict__ x) {
    extern __shared__ float sm[];
    float* R   = sm;
    float* I   = sm + UBUF;
    float* twR = sm + 2 * UBUF;
    float* twI = twR + 64;

    const int tid = threadIdx.x;
    const int img = blockIdx.x;

    if (tid < 64) {
        float s, c;
        sincospif(-(float)tid / 64.0f, &s, &c);
        twR[tid] = c; twI[tid] = s;
    }

    const float* src = x + (size_t)img * (H_ * W_);
    for (int t = tid; t < 64 * 128; t += NT_F) {
        int p = t >> 7, c = t & 127;
        int cb = brev7(c);
        R[p * RPIT + cb] = src[(2 * p) * 128 + c];
        I[p * RPIT + cb] = src[(2 * p) * 128 + 128 + c];
    }
    __syncthreads();

    pass4_rows<1>(R, I, twR, twI); __syncthreads();
    pass4_rows<3>(R, I, twR, twI); __syncthreads();
    pass4_rows<5>(R, I, twR, twI); __syncthreads();
    pass2_rows   (R, I, twR, twI); __syncthreads();

    float u0r[9], u0i[9], u1r[9], u1i[9];
    #pragma unroll
    for (int n = 0; n < 9; n++) {
        int it = tid + n * NT_F;
        if (it < 64 * 65) {
            int k = it % 65, p = it / 65;
            int m = (128 - k) & 127;
            float a = R[p * RPIT + k], b = I[p * RPIT + k];
            float c2 = R[p * RPIT + m], d = I[p * RPIT + m];
            u0r[n] = 0.5f * (a + c2); u0i[n] = 0.5f * (b - d);
            u1r[n] = 0.5f * (b + d);  u1i[n] = 0.5f * (c2 - a);
        }
    }
    __syncthreads();
    #pragma unroll
    for (int n = 0; n < 9; n++) {
        int it = tid + n * NT_F;
        if (it < 64 * 65) {
            int k = it % 65, p = it / 65;
            int h0 = brev7(2 * p), h1 = brev7(2 * p + 1);
            R[h0 * CPIT + k] = u0r[n]; I[h0 * CPIT + k] = u0i[n];
            R[h1 * CPIT + k] = u1r[n]; I[h1 * CPIT + k] = u1i[n];
        }
    }
    __syncthreads();

    pass4_cols<1>(R, I, twR, twI); __syncthreads();
    pass4_cols<3>(R, I, twR, twI); __syncthreads();
    pass4_cols<5>(R, I, twR, twI); __syncthreads();
    pass2_cols   (R, I, twR, twI); __syncthreads();

    float* dR = g_specR + (size_t)img * F_;
    float* dI = g_specI + (size_t)img * F_;
    const float sc = 1.0f / 128.0f;
    for (int t = tid; t < F_; t += NT_F) {
        dR[t] = R[t] * sc;
        dI[t] = I[t] * sc;
    }
}

// ---------------------------------------------------------------------------
// Tensor-core mixer via mma.sync (HMMA bf16, split hi/lo K-expansion).
// One CTA = one (b,g) x 64-freq tile. M=128 out-ch, N=64 freq, K=128 in-ch.
// accOr += Wr*Xr (3 passes), accP += Wi*Xi (3), accOi += Wi*Xr + Wr*Xi (6).
// Or = accOr - accP + br ; Oi = accOi + bi.
// ---------------------------------------------------------------------------
__device__ __forceinline__ void mma16816(float* d, const uint32_t* a, const uint32_t* b) {
    asm volatile("mma.sync.aligned.m16n8k16.row.col.f32.bf16.bf16.f32 "
        "{%0,%1,%2,%3}, {%4,%5,%6,%7}, {%8,%9}, {%0,%1,%2,%3};"
        : "+f"(d[0]), "+f"(d[1]), "+f"(d[2]), "+f"(d[3])
        : "r"(a[0]), "r"(a[1]), "r"(a[2]), "r"(a[3]), "r"(b[0]), "r"(b[1]));
}

__device__ __forceinline__ void ldA(uint32_t* a, const unsigned short* Wp,
                                    int row, int k0, int tig) {
    const unsigned short* p = Wp + row * WP + k0 + tig * 2;
    a[0] = *(const uint32_t*)p;
    a[1] = *(const uint32_t*)(p + 8 * WP);
    a[2] = *(const uint32_t*)(p + 8);
    a[3] = *(const uint32_t*)(p + 8 * WP + 8);
}
__device__ __forceinline__ void ldB(uint32_t* bb, const unsigned short* Xp,
                                    int row, int k0, int tig) {
    const unsigned short* p = Xp + row * WP + k0 + tig * 2;
    bb[0] = *(const uint32_t*)p;
    bb[1] = *(const uint32_t*)(p + 8);
}

__device__ __forceinline__ void gemm_layer(const unsigned short* smW,
                                           const unsigned short* smX,
                                           float* aOr, float* aP, float* aOi,
                                           int warp_m, int warp_n, int gid, int tig) {
    #pragma unroll 1
    for (int kk = 0; kk < 8; kk++) {
        const int k0 = kk * 16;
        uint32_t A[4][2][4];
        #pragma unroll
        for (int pl = 0; pl < 4; pl++)
            #pragma unroll
            for (int mt = 0; mt < 2; mt++)
                ldA(A[pl][mt], smW + pl * PLW, warp_m + mt * 16 + gid, k0, tig);
        uint32_t Bf[4][4][2];
        #pragma unroll
        for (int pl = 0; pl < 4; pl++)
            #pragma unroll
            for (int nt = 0; nt < 4; nt++)
                ldB(Bf[pl][nt], smX + pl * PLX, warp_n + nt * 8 + gid, k0, tig);
        #pragma unroll
        for (int mt = 0; mt < 2; mt++)
            #pragma unroll
            for (int nt = 0; nt < 4; nt++) {
                float* dOr = aOr + (mt * 4 + nt) * 4;
                float* dP  = aP  + (mt * 4 + nt) * 4;
                float* dOi = aOi + (mt * 4 + nt) * 4;
                mma16816(dOr, A[0][mt], Bf[0][nt]);   // WrH*XrH
                mma16816(dOr, A[1][mt], Bf[0][nt]);   // WrL*XrH
                mma16816(dOr, A[0][mt], Bf[1][nt]);   // WrH*XrL
                mma16816(dP,  A[2][mt], Bf[2][nt]);   // WiH*XiH
                mma16816(dP,  A[3][mt], Bf[2][nt]);   // WiL*XiH
                mma16816(dP,  A[2][mt], Bf[3][nt]);   // WiH*XiL
                mma16816(dOi, A[2][mt], Bf[0][nt]);   // WiH*XrH
                mma16816(dOi, A[3][mt], Bf[0][nt]);   // WiL*XrH
                mma16816(dOi, A[2][mt], Bf[1][nt]);   // WiH*XrL
                mma16816(dOi, A[0][mt], Bf[2][nt]);   // WrH*XiH
                mma16816(dOi, A[1][mt], Bf[2][nt]);   // WrL*XiH
                mma16816(dOi, A[0][mt], Bf[3][nt]);   // WrH*XiL
            }
    }
}

#define SM_MIX (4 * PLW * 2 + 4 * PLX * 2)   // 139264 + 69632 = 208896 B

__global__ void __launch_bounds__(256, 1)
kmix_mma(const float* __restrict__ b1, const float* __restrict__ b2) {
    extern __shared__ unsigned short smix[];
    unsigned short* smW = smix;              // 4 W planes
    unsigned short* smX = smix + 4 * PLW;    // 4 X/O1 planes

    const int tid = threadIdx.x;
    const int wid = tid >> 5, lane = tid & 31;
    const int gid = lane >> 2, tig = lane & 3;
    const int warp_m = (wid & 3) * 32;
    const int warp_n = (wid >> 2) * 32;
    const int ft = blockIdx.x;               // 0..129
    const int bg = blockIdx.y;               // 0..31
    const int b = bg >> 2, g = bg & 3;

    const size_t specbase = ((size_t)b * C_ + (size_t)g * D_) * F_ + (size_t)ft * 64;

    // ---- load W1 planes + build X planes ----
    {
        const float4* ws = (const float4*)(g_wimg + (size_t)(0 * 4 + g) * 4 * PLW);
        float4* wd = (float4*)smW;
        for (int i = tid; i < 4 * PLW / 8; i += 256) wd[i] = ws[i];
    }
    for (int it = tid; it < 128 * 64; it += 256) {
        int c = it >> 6, f = it & 63;
        float vr = g_specR[specbase + (size_t)c * F_ + f];
        float vi = g_specI[specbase + (size_t)c * F_ + f];
        unsigned short rh, rl, ih, il;
        split_bf16(vr, rh, rl);
        split_bf16(vi, ih, il);
        int o = f * WP + c;
        smX[o] = rh; smX[PLX + o] = rl; smX[2 * PLX + o] = ih; smX[3 * PLX + o] = il;
    }
    __syncthreads();

    float aOr[32], aP[32], aOi[32];
    #pragma unroll
    for (int i = 0; i < 32; i++) { aOr[i] = 0.f; aP[i] = 0.f; aOi[i] = 0.f; }

    // ================= Layer 1 =================
    gemm_layer(smW, smX, aOr, aP, aOi, warp_m, warp_n, gid, tig);
    __syncthreads();

    // epilogue 1: bias + relu, split, write O1 planes (X area); load W2
    {
        #pragma unroll
        for (int mt = 0; mt < 2; mt++) {
            int r0 = warp_m + mt * 16 + gid;
            float br0 = b1[g * D_ + r0],      br1 = b1[g * D_ + r0 + 8];
            float bi0 = b1[(G_ + g) * D_ + r0], bi1 = b1[(G_ + g) * D_ + r0 + 8];
            #pragma unroll
            for (int nt = 0; nt < 4; nt++) {
                int c0 = warp_n + nt * 8 + tig * 2;
                int ai = (mt * 4 + nt) * 4;
                #pragma unroll
                for (int e = 0; e < 4; e++) {
                    int row = (e >= 2) ? r0 + 8 : r0;
                    int col = c0 + (e & 1);
                    float brv = (e >= 2) ? br1 : br0;
                    float biv = (e >= 2) ? bi1 : bi0;
                    float vr = aOr[ai + e] - aP[ai + e] + brv; vr = vr > 0.f ? vr : 0.f;
                    float vi = aOi[ai + e] + biv;              vi = vi > 0.f ? vi : 0.f;
                    unsigned short rh, rl, ih, il;
                    split_bf16(vr, rh, rl);
                    split_bf16(vi, ih, il);
                    int o = col * WP + row;
                    smX[o] = rh; smX[PLX + o] = rl;
                    smX[2 * PLX + o] = ih; smX[3 * PLX + o] = il;
                }
            }
        }
        const float4* ws = (const float4*)(g_wimg + (size_t)(1 * 4 + g) * 4 * PLW);
        float4* wd = (float4*)smW;
        for (int i = tid; i < 4 * PLW / 8; i += 256) wd[i] = ws[i];
    }
    __syncthreads();

    #pragma unroll
    for (int i = 0; i < 32; i++) { aOr[i] = 0.f; aP[i] = 0.f; aOi[i] = 0.f; }

    // ================= Layer 2 =================
    gemm_layer(smW, smX, aOr, aP, aOi, warp_m, warp_n, gid, tig);

    // epilogue 2: bias, multiply by origin, store
    {
        #pragma unroll
        for (int mt = 0; mt < 2; mt++) {
            int r0 = warp_m + mt * 16 + gid;
            float br0 = b2[g * D_ + r0],        br1 = b2[g * D_ + r0 + 8];
            float bi0 = b2[(G_ + g) * D_ + r0], bi1 = b2[(G_ + g) * D_ + r0 + 8];
            #pragma unroll
            for (int nt = 0; nt < 4; nt++) {
                int c0 = warp_n + nt * 8 + tig * 2;
                int ai = (mt * 4 + nt) * 4;
                #pragma unroll
                for (int rp = 0; rp < 2; rp++) {          // row pair: e={0,1} / {2,3}
                    int row = r0 + rp * 8;
                    float brv = rp ? br1 : br0;
                    float biv = rp ? bi1 : bi0;
                    size_t gi = specbase + (size_t)row * F_ + c0;
                    float2 xr = *(const float2*)&g_specR[gi];
                    float2 xi = *(const float2*)&g_specI[gi];
                    float vr0 = aOr[ai + rp * 2]     - aP[ai + rp * 2]     + brv;
                    float vi0 = aOi[ai + rp * 2]     + biv;
                    float vr1 = aOr[ai + rp * 2 + 1] - aP[ai + rp * 2 + 1] + brv;
                    float vi1 = aOi[ai + rp * 2 + 1] + biv;
                    float2 orv, oiv;
                    orv.x = vr0 * xr.x - vi0 * xi.x;
                    oiv.x = vr0 * xi.x + vi0 * xr.x;
                    orv.y = vr1 * xr.y - vi1 * xi.y;
                    oiv.y = vr1 * xi.y + vi1 * xr.y;
                    *(float2*)&g_outR[gi] = orv;
                    *(float2*)&g_outI[gi] = oiv;
                }
            }
        }
    }
}

// ---------------------------------------------------------------------------
__global__ void __launch_bounds__(NT_F, 2) kfft_inv(float* __restrict__ y) {
    extern __shared__ float sm[];
    float* R   = sm;
    float* I   = sm + UBUF;
    float* twR = sm + 2 * UBUF;
    float* twI = twR + 64;

    const int tid = threadIdx.x;
    const int img = blockIdx.x;

    if (tid < 64) {
        float s, c;
        sincospif((float)tid / 64.0f, &s, &c);
        twR[tid] = c; twI[tid] = s;
    }

    const float* srcR = g_outR + (size_t)img * F_;
    const float* srcI = g_outI + (size_t)img * F_;
    for (int t = tid; t < F_; t += NT_F) {
        int h = t / WF_, k = t - h * WF_;
        int hb = brev7(h);
        R[hb * CPIT + k] = srcR[t];
        I[hb * CPIT + k] = srcI[t];
    }
    __syncthreads();

    pass4_cols<1>(R, I, twR, twI); __syncthreads();
    pass4_cols<3>(R, I, twR, twI); __syncthreads();
    pass4_cols<5>(R, I, twR, twI); __syncthreads();
    pass2_cols   (R, I, twR, twI); __syncthreads();

    float zr[16], zi[16];
    #pragma unroll
    for (int n = 0; n < 16; n++) {
        int it = tid + n * NT_F;
        int w = it & 127, p = it >> 7;
        int r0 = (2 * p) * CPIT, r1 = r0 + CPIT;
        if (w <= 64) {
            float x0r = R[r0 + w], x0i = I[r0 + w];
            float x1r = R[r1 + w], x1i = I[r1 + w];
            if (w == 0 || w == 64) { x0i = 0.f; x1i = 0.f; }
            zr[n] = x0r - x1i;
            zi[n] = x0i + x1r;
        } else {
            int m = 128 - w;
            float x0r = R[r0 + m], x0i = I[r0 + m];
            float x1r = R[r1 + m], x1i = I[r1 + m];
            zr[n] = x0r + x1i;
            zi[n] = x1r - x0i;
        }
    }
    __syncthreads();
    #pragma unroll
    for (int n = 0; n < 16; n++) {
        int it = tid + n * NT_F;
        int w = it & 127, p = it >> 7;
        int wb = brev7(w);
        R[p * RPIT + wb] = zr[n];
        I[p * RPIT + wb] = zi[n];
    }
    __syncthreads();

    pass4_rows<1>(R, I, twR, twI); __syncthreads();
    pass4_rows<3>(R, I, twR, twI); __syncthreads();
    pass4_rows<5>(R, I, twR, twI); __syncthreads();
    pass2_rows   (R, I, twR, twI); __syncthreads();

    float* dst = y + (size_t)img * (H_ * W_);
    const float sc = 1.0f / 128.0f;
    for (int t = tid; t < 64 * 128; t += NT_F) {
        int p = t >> 7, c = t & 127;
        dst[(2 * p) * 128 + c]       = R[p * RPIT + c] * sc;
        dst[(2 * p) * 128 + 128 + c] = I[p * RPIT + c] * sc;
    }
}

// ---------------------------------------------------------------------------
extern "C" void kernel_launch(void* const* d_in, const int* in_sizes, int n_in,
                              void* d_out, int out_size) {
    const float* x  = (const float*)d_in[0];
    const float* w1 = (const float*)d_in[1];
    const float* w2 = (const float*)d_in[2];
    const float* b1 = (const float*)d_in[3];
    const float* b2 = (const float*)d_in[4];
    float* y = (float*)d_out;

    const int smFFT = (2 * UBUF + 128) * (int)sizeof(float);   // ~65.5 KB

    cudaFuncSetAttribute(kfft_fwd, cudaFuncAttributeMaxDynamicSharedMemorySize, smFFT);
    cudaFuncSetAttribute(kmix_mma, cudaFuncAttributeMaxDynamicSharedMemorySize, SM_MIX);
    cudaFuncSetAttribute(kfft_inv, cudaFuncAttributeMaxDynamicSharedMemorySize, smFFT);

    wprep<<<1024, 256>>>(w1, w2);
    kfft_fwd<<<NIMG, NT_F, smFFT>>>(x);
    kmix_mma<<<dim3(130, 32), 256, SM_MIX>>>(b1, b2);
    kfft_inv<<<NIMG, NT_F, smFFT>>>(y);
}